// round 11
// baseline (speedup 1.0000x reference)
#include <cuda_runtime.h>
#include <cuda_fp16.h>
#include <cstdint>

#define N_NODES 20000
#define N_EDGES 320000
#define F_IN   256
#define F_HID  512

// ---------------- device scratch (no allocs allowed) ----------------
__device__ float    g_acc[N_NODES * F_IN];        // (1+eps)*x + segment_sum
__device__ uint32_t g_W1h_e[F_HID * F_IN / 2];    // [n=512][128 words] half2, k-permuted
__device__ uint32_t g_W2h_e[F_IN * F_HID / 2];    // [n=256][256 words]
__device__ uint32_t g_W1h_n[F_HID * F_IN / 2];
__device__ uint32_t g_W2h_n[F_IN * F_HID / 2];

// ---------------- helpers ----------------
__device__ __forceinline__ uint32_t smem_u32(const void* p) {
    uint32_t a;
    asm("{ .reg .u64 t; cvta.to.shared.u64 t, %1; cvt.u32.u64 %0, t; }" : "=r"(a) : "l"(p));
    return a;
}
__device__ __forceinline__ uint32_t packh2(float a, float b) {
    __half2 h = __floats2half2_rn(a, b);
    return *reinterpret_cast<uint32_t*>(&h);
}
// m16n8k16 fp16 mma, f32 accum: d += a * b
__device__ __forceinline__ void mma16(float* d, uint32_t a0, uint32_t a1,
                                      uint32_t a2, uint32_t a3,
                                      uint32_t b0, uint32_t b1) {
    asm volatile(
        "mma.sync.aligned.m16n8k16.row.col.f32.f16.f16.f32 "
        "{%0,%1,%2,%3}, {%4,%5,%6,%7}, {%8,%9}, {%0,%1,%2,%3};"
        : "+f"(d[0]), "+f"(d[1]), "+f"(d[2]), "+f"(d[3])
        : "r"(a0), "r"(a1), "r"(a2), "r"(a3), "r"(b0), "r"(b1));
}
__device__ __forceinline__ void cp16(uint32_t sdst, const void* gsrc) {
    asm volatile("cp.async.ca.shared.global [%0], [%1], 16;" :: "r"(sdst), "l"(gsrc) : "memory");
}
#define CP_COMMIT() asm volatile("cp.async.commit_group;" ::: "memory")
#define CP_WAIT0()  asm volatile("cp.async.wait_group 0;" ::: "memory")

// word-level k-interleave: position p holds orig word (p&1)?(p>>1)+4:(p>>1);
// orig word j goes to position (j<4)? 2j : 2j-7
__device__ __forceinline__ int permpos(int j) { return (j < 4) ? 2 * j : 2 * j - 7; }

// ---------------- fused prep: init g_acc + convert all 4 weights ----------------
__global__ void prep_kernel(const float* __restrict__ node_feat,
                            const float* __restrict__ eps,
                            const float* __restrict__ We1, const float* __restrict__ We2,
                            const float* __restrict__ Wn1, const float* __restrict__ Wn2) {
    int bid = blockIdx.x;
    int tid = threadIdx.x;
    if (bid < 5000) {
        const float s = 1.0f + eps[0];
        int i = bid * 256 + tid;
        float4 v = reinterpret_cast<const float4*>(node_feat)[i];
        v.x *= s; v.y *= s; v.z *= s; v.w *= s;
        reinterpret_cast<float4*>(g_acc)[i] = v;
        return;
    }
    int b2 = bid - 5000;
    int w = b2 >> 8;                       // 0..3
    int idx = (b2 & 255) * 256 + tid;      // 0..65535
    const float* in; uint32_t* out; int K, N;
    if      (w == 0) { in = We1; out = g_W1h_e; K = F_IN;  N = F_HID; }
    else if (w == 1) { in = We2; out = g_W2h_e; K = F_HID; N = F_IN;  }
    else if (w == 2) { in = Wn1; out = g_W1h_n; K = F_IN;  N = F_HID; }
    else             { in = Wn2; out = g_W2h_n; K = F_HID; N = F_IN;  }
    int KW = K >> 1;
    int n = idx / KW;
    int p = idx - n * KW;
    int j = p & 7;
    int o = (p & ~7) + ((j & 1) ? (j >> 1) + 4 : (j >> 1));   // orig word
    out[idx] = packh2(in[(2 * o) * N + n], in[(2 * o + 1) * N + n]);
}

__global__ void noop_kernel() {}

// ---------------- fused 2-layer MLP, fp16 mma, 512 threads ----------------
// 128 rows/CTA, 512 threads (16 warps = 4 row x 4 col). 4 warps/SMSP.
// SMEM layout identical to round 10 (142336 B).
#define OFF_HW  17408
#define OFF_WB  22528
#define WB_BYTES 24576u
#define OFF_B1  34816
#define OFF_B2  35328
#define SMEM_WORDS 35584
#define SMEM_BYTES (SMEM_WORDS * 4)

template <bool EDGE>
__global__ void __launch_bounds__(512, 1)
gine_mma(const float* __restrict__ Xin,
         const uint32_t* __restrict__ W1w, const float* __restrict__ b1,
         const uint32_t* __restrict__ W2w, const float* __restrict__ b2,
         const float* __restrict__ node_feat,
         const int* __restrict__ src, const int* __restrict__ dst,
         float* __restrict__ out, int M_total) {
    extern __shared__ uint32_t smw[];
    uint32_t* Xw  = smw;
    uint32_t* Hw  = smw + OFF_HW;
    uint32_t* Wb  = smw + OFF_WB;
    float*    b1s = reinterpret_cast<float*>(smw + OFF_B1);
    float*    b2s = reinterpret_cast<float*>(smw + OFF_B2);
    const uint32_t wb_u32 = smem_u32(Wb);

    const int tid  = threadIdx.x;
    const int lane = tid & 31;
    const int grp  = lane >> 2;     // 0..7
    const int tig  = lane & 3;      // 0..3
    const int wid  = tid >> 5;      // 0..15
    const int wr   = wid & 3;       // rows wr*32..+31
    const int wc   = wid >> 2;      // 0..3
    const int m0   = blockIdx.x * 128;

    const float4* X4 = reinterpret_cast<const float4*>(Xin);

    // biases
    b1s[tid] = b1[tid];
    if (tid < 256) b2s[tid] = b2[tid];

    // stage X tile [128][256] -> half2 words, k-permuted per 8-word group
    #pragma unroll
    for (int it = 0; it < 16; ++it) {
        int i = it * 512 + tid;
        int r = i >> 6, c4 = i & 63;
        int gr = m0 + r; if (gr >= M_total) gr = M_total - 1;
        float4 v = X4[gr * 64 + c4];
        int w0 = 2 * c4;
        int base = w0 & ~7;
        int j0 = w0 & 7;
        uint32_t* rp = Xw + r * 136 + base;
        rp[permpos(j0)]     = packh2(v.x, v.y);
        rp[permpos(j0 + 1)] = packh2(v.z, v.w);
    }

    float acc2[2][8][4];
    #pragma unroll
    for (int mi = 0; mi < 2; ++mi)
        #pragma unroll
        for (int ni = 0; ni < 8; ++ni)
            #pragma unroll
            for (int q = 0; q < 4; ++q) acc2[mi][ni][q] = 0.f;

    // ---- staging (cp.async into Wb[buf], row stride 24 words) ----
    auto stage_w1 = [&](int hc, int kt, int buf) {
        if (tid < 256) {
            int r = tid >> 2, g = tid & 3;     // 64 rows x 4 groups
            cp16(wb_u32 + (uint32_t)buf * WB_BYTES + (uint32_t)(r * 24 + g * 4) * 4u,
                 W1w + (hc * 64 + r) * 128 + kt * 16 + g * 4);
        }
    };
    auto stage_w2 = [&](int hc, int kt2, int buf) {
        #pragma unroll
        for (int it = 0; it < 2; ++it) {
            int i = it * 512 + tid;
            int r = i >> 2, g = i & 3;         // 256 rows x 4 groups
            cp16(wb_u32 + (uint32_t)buf * WB_BYTES + (uint32_t)(r * 24 + g * 4) * 4u,
                 W2w + r * 256 + hc * 32 + kt2 * 16 + g * 4);
        }
    };

    stage_w1(0, 0, 0);
    CP_COMMIT();
    int cur = 0;

    const int rowA0 = (wr * 32 + grp) * 136;
    const int rowH0 = (wr * 32 + grp) * 40;

    for (int hc = 0; hc < 8; ++hc) {
        // ===== GEMM1: H chunk [128 x 64] = X @ W1 =====
        float acc1[2][2][4];
        #pragma unroll
        for (int mi = 0; mi < 2; ++mi)
            #pragma unroll
            for (int ni = 0; ni < 2; ++ni)
                #pragma unroll
                for (int q = 0; q < 4; ++q) acc1[mi][ni][q] = 0.f;

        for (int kt = 0; kt < 8; ++kt) {       // 128 words K, slices of 16
            CP_WAIT0();
            __syncthreads();
            if (kt < 7) stage_w1(hc, kt + 1, (cur + 1) & 1);
            else        stage_w2(hc, 0, (cur + 1) & 1);
            CP_COMMIT();
            const uint32_t* Wc = Wb + (cur & 1) * 6144;
            ++cur;
            #pragma unroll
            for (int k16 = 0; k16 < 2; ++k16) {
                const int kwb = kt * 16 + k16 * 8 + 2 * tig;
                uint2 xa0 = *reinterpret_cast<const uint2*>(Xw + rowA0 + kwb);
                uint2 xa1 = *reinterpret_cast<const uint2*>(Xw + rowA0 + 8 * 136 + kwb);
                uint2 xa2 = *reinterpret_cast<const uint2*>(Xw + rowA0 + 16 * 136 + kwb);
                uint2 xa3 = *reinterpret_cast<const uint2*>(Xw + rowA0 + 24 * 136 + kwb);
                #pragma unroll
                for (int ni = 0; ni < 2; ++ni) {
                    const int nb = wc * 16 + ni * 8 + grp;
                    uint2 fb = *reinterpret_cast<const uint2*>(Wc + nb * 24 + k16 * 8 + 2 * tig);
                    mma16(acc1[0][ni], xa0.x, xa1.x, xa0.y, xa1.y, fb.x, fb.y);
                    mma16(acc1[1][ni], xa2.x, xa3.x, xa2.y, xa3.y, fb.x, fb.y);
                }
            }
        }
        // epilogue1: Hw = half2(relu(acc1 + b1)), k-permuted words
        #pragma unroll
        for (int mi = 0; mi < 2; ++mi)
            #pragma unroll
            for (int ni = 0; ni < 2; ++ni) {
                const int colg = wc * 16 + ni * 8;
                const int bcol = hc * 64 + colg + 2 * tig;
                const float bb0 = b1s[bcol], bb1 = b1s[bcol + 1];
                const int o = wc * 8 + ni * 4 + tig;           // orig word in 32-word H chunk
                const int pos = (o & ~7) + permpos(o & 7);
                uint32_t* h0 = Hw + rowH0 + mi * 16 * 40 + pos;
                h0[0]      = packh2(fmaxf(acc1[mi][ni][0] + bb0, 0.f),
                                    fmaxf(acc1[mi][ni][1] + bb1, 0.f));
                h0[8 * 40] = packh2(fmaxf(acc1[mi][ni][2] + bb0, 0.f),
                                    fmaxf(acc1[mi][ni][3] + bb1, 0.f));
            }
        // ===== GEMM2 partial: acc2 += Hchunk @ W2 slice =====
        for (int kt2 = 0; kt2 < 2; ++kt2) {
            CP_WAIT0();
            __syncthreads();
            if (kt2 < 1)      stage_w2(hc, 1, (cur + 1) & 1);
            else if (hc < 7)  stage_w1(hc + 1, 0, (cur + 1) & 1);
            CP_COMMIT();
            const uint32_t* Wc = Wb + (cur & 1) * 6144;
            ++cur;
            #pragma unroll
            for (int k16 = 0; k16 < 2; ++k16) {
                const int kwb = kt2 * 16 + k16 * 8 + 2 * tig;
                uint2 ha0 = *reinterpret_cast<const uint2*>(Hw + rowH0 + kwb);
                uint2 ha1 = *reinterpret_cast<const uint2*>(Hw + rowH0 + 8 * 40 + kwb);
                uint2 ha2 = *reinterpret_cast<const uint2*>(Hw + rowH0 + 16 * 40 + kwb);
                uint2 ha3 = *reinterpret_cast<const uint2*>(Hw + rowH0 + 24 * 40 + kwb);
                #pragma unroll
                for (int ni = 0; ni < 8; ++ni) {
                    const int nb = wc * 64 + ni * 8 + grp;
                    uint2 fb = *reinterpret_cast<const uint2*>(Wc + nb * 24 + k16 * 8 + 2 * tig);
                    mma16(acc2[0][ni], ha0.x, ha1.x, ha0.y, ha1.y, fb.x, fb.y);
                    mma16(acc2[1][ni], ha2.x, ha3.x, ha2.y, ha3.y, fb.x, fb.y);
                }
            }
        }
    }

    // ===== final epilogue: two 128-col halves restaged through SMEM =====
    float* Of = reinterpret_cast<float*>(smw);        // [128][132] floats (fits in Xw area)
    for (int h = 0; h < 2; ++h) {
        __syncthreads();
        if ((wc >> 1) == h) {                 // wc 0,1 -> cols 0..127 ; wc 2,3 -> 128..255
            #pragma unroll
            for (int mi = 0; mi < 2; ++mi)
                #pragma unroll
                for (int ni = 0; ni < 8; ++ni) {
                    int row = wr * 32 + mi * 16 + grp;
                    int col = (wc & 1) * 64 + ni * 8 + 2 * tig;
                    Of[row * 132 + col]           = acc2[mi][ni][0];
                    Of[row * 132 + col + 1]       = acc2[mi][ni][1];
                    Of[(row + 8) * 132 + col]     = acc2[mi][ni][2];
                    Of[(row + 8) * 132 + col + 1] = acc2[mi][ni][3];
                }
        }
        __syncthreads();
        #pragma unroll 4
        for (int it = 0; it < 8; ++it) {
            int r   = it * 16 + (tid >> 5);
            int c4h = tid & 31;
            int c4  = h * 32 + c4h;
            int gr  = m0 + r;
            float4 v  = *reinterpret_cast<float4*>(Of + r * 132 + c4h * 4);
            float4 bb = *reinterpret_cast<float4*>(b2s + c4 * 4);
            v.x += bb.x; v.y += bb.y; v.z += bb.z; v.w += bb.w;
            if (EDGE) {
                int s = src[gr];
                int d = dst[gr];
                float4 nf = reinterpret_cast<const float4*>(node_feat)[s * 64 + c4];
                v.x = fmaxf(v.x + nf.x, 0.f);
                v.y = fmaxf(v.y + nf.y, 0.f);
                v.z = fmaxf(v.z + nf.z, 0.f);
                v.w = fmaxf(v.w + nf.w, 0.f);
                float* p = g_acc + (size_t)d * 256 + c4 * 4;
                asm volatile("red.global.add.v4.f32 [%0], {%1, %2, %3, %4};"
                             :: "l"(p), "f"(v.x), "f"(v.y), "f"(v.z), "f"(v.w)
                             : "memory");
            } else if (gr < M_total) {
                reinterpret_cast<float4*>(out)[gr * 64 + c4] = v;
            }
        }
    }
}

// ---------------------------------------------------------------------------
extern "C" void kernel_launch(void* const* d_in, const int* in_sizes, int n_in,
                              void* d_out, int out_size) {
    const float* node_feat = (const float*)d_in[0];
    const float* edge_feat = (const float*)d_in[1];
    const int*   src       = (const int*)d_in[2];
    const int*   dst       = (const int*)d_in[3];
    const float* We1       = (const float*)d_in[4];
    const float* be1       = (const float*)d_in[5];
    const float* We2       = (const float*)d_in[6];
    const float* be2       = (const float*)d_in[7];
    const float* Wn1       = (const float*)d_in[8];
    const float* bn1       = (const float*)d_in[9];
    const float* Wn2       = (const float*)d_in[10];
    const float* bn2       = (const float*)d_in[11];
    const float* eps       = (const float*)d_in[12];
    float* out = (float*)d_out;

    cudaFuncSetAttribute(gine_mma<true>,
                         cudaFuncAttributeMaxDynamicSharedMemorySize, SMEM_BYTES);
    cudaFuncSetAttribute(gine_mma<false>,
                         cudaFuncAttributeMaxDynamicSharedMemorySize, SMEM_BYTES);

    uint32_t *W1e, *W2e, *W1n, *W2n;
    float *accp;
    cudaGetSymbolAddress((void**)&W1e, g_W1h_e);
    cudaGetSymbolAddress((void**)&W2e, g_W2h_e);
    cudaGetSymbolAddress((void**)&W1n, g_W1h_n);
    cudaGetSymbolAddress((void**)&W2n, g_W2h_n);
    cudaGetSymbolAddress((void**)&accp, g_acc);

    // 6-launch cycle; edge kernel at index 3 so ncu's capture slot lands on it.
    // 0) prep
    prep_kernel<<<6024, 256>>>(node_feat, eps, We1, We2, Wn1, Wn2);
    // 1,2) spacers
    noop_kernel<<<1, 1>>>();
    noop_kernel<<<1, 1>>>();
    // 3) edge MLP + gather/relu/scatter-add  (2500 CTAs)
    gine_mma<true><<<N_EDGES / 128, 512, SMEM_BYTES>>>(
        edge_feat, W1e, be1, W2e, be2, node_feat, src, dst, nullptr, N_EDGES);
    // 4) node MLP on acc -> out              (157 CTAs)
    gine_mma<false><<<(N_NODES + 127) / 128, 512, SMEM_BYTES>>>(
        accp, W1n, bn1, W2n, bn2, nullptr, nullptr, nullptr, out, N_NODES);
    // 5) spacer
    noop_kernel<<<1, 1>>>();
}